// round 9
// baseline (speedup 1.0000x reference)
#include <cuda_runtime.h>
#include <cstdint>

#define NN 16384
#define NE 4096
#define DD 256
#define KS 4             // k-splits for gemm1
#define NCH (NN / KS)    // 4096 nodes per split

// ---------------- scratch (device globals; no allocation allowed) ----------------
__device__ float g_xw1 [NN * DD];
__device__ float g_xw1T[DD * NN];   // tf32-rounded transpose of xw1
__device__ float g_fe  [NE * DD];
__device__ float g_g   [NE * DD];
__device__ float g_gT  [DD * NE];   // tf32-rounded transpose of g
__device__ float g_s1  [NN];
__device__ float g_r   [NN];
__device__ float g_c   [NE];
__device__ float g_p1  [KS * NE * DD];   // gemm1 k-split partials (16.8 MB)
__device__ float g_pcs [KS * NE];        // gemm1 colsum partials

__device__ __forceinline__ float lrelu(float v) { return v > 0.0f ? v : 0.1f * v; }

// exp(8*tanh(z/8)) via tanh(y) = 1 - 2/(e^{2y}+1) (exact, safe at +-inf)
__device__ __forceinline__ float softexp8(float z) {
    float v = __expf(z * 0.25f);
    float t = 1.0f - __fdividef(2.0f, v + 1.0f);
    return __expf(8.0f * t);
}

__device__ __forceinline__ uint32_t tf32c(float x) {
    uint32_t r; asm("cvt.rna.tf32.f32 %0, %1;" : "=r"(r) : "f"(x)); return r;
}

__device__ __forceinline__ uint32_t su32(const void* p) {
    uint32_t a;
    asm("{ .reg .u64 t; cvta.to.shared.u64 t, %1; cvt.u32.u64 %0, t; }" : "=r"(a) : "l"(p));
    return a;
}

__device__ __forceinline__ void mma8(float* d, const uint32_t a[4],
                                     uint32_t b0, uint32_t b1) {
    asm volatile(
        "mma.sync.aligned.m16n8k8.row.col.f32.tf32.tf32.f32 "
        "{%0,%1,%2,%3}, {%4,%5,%6,%7}, {%8,%9}, {%0,%1,%2,%3};"
        : "+f"(d[0]), "+f"(d[1]), "+f"(d[2]), "+f"(d[3])
        : "r"(a[0]), "r"(a[1]), "r"(a[2]), "r"(a[3]), "r"(b0), "r"(b1));
}

__device__ __forceinline__ void cpa16(uint32_t dst, const void* src) {
    asm volatile("cp.async.ca.shared.global [%0], [%1], 16;" :: "r"(dst), "l"(src));
}
#define CP_COMMIT() asm volatile("cp.async.commit_group;" ::: "memory")
#define CP_WAIT0()  asm volatile("cp.async.wait_group 0;" ::: "memory")

#define PAD 36
#define A_ST (128 * PAD)       // 4608 u32 per A buffer
#define B_ST (256 * PAD)       // 9216 u32 per B buffer
#define OFF_A0 0
#define OFF_A1 A_ST
#define OFF_B0 (2 * A_ST)
#define OFF_B1 (2 * A_ST + B_ST)
#define OFF_RD (2 * A_ST + 2 * B_ST)
#define SM_U32 (OFF_RD + 512)
#define SMEMB (SM_U32 * 4)     // 112640 bytes

// warp-tile MMA over one 32-K stage: CTA tile 128x256, warp tile 64x64 (8 warps, 2x4)
__device__ __forceinline__ void mma_stage64(const uint32_t* __restrict__ As,
                                            const uint32_t* __restrict__ Bs,
                                            float acc[4][8][4],
                                            int lane, int wm, int wn) {
    const int qr = lane >> 2, qc = lane & 3;
#pragma unroll
    for (int ks = 0; ks < 4; ks++) {
        const int kk = ks * 8;
        uint32_t af[4][4];
#pragma unroll
        for (int mt = 0; mt < 4; mt++) {
            const uint32_t* ap = As + (wm * 64 + mt * 16 + qr) * PAD + kk + qc;
            af[mt][0] = ap[0];
            af[mt][1] = ap[8 * PAD];
            af[mt][2] = ap[4];
            af[mt][3] = ap[8 * PAD + 4];
        }
#pragma unroll
        for (int nt = 0; nt < 8; nt++) {
            const uint32_t* bp = Bs + (wn * 64 + nt * 8 + qr) * PAD + kk + qc;
            uint32_t b0 = bp[0], b1 = bp[4];
#pragma unroll
            for (int mt = 0; mt < 4; mt++)
                mma8(acc[mt][nt], af[mt], b0, b1);
        }
    }
}

// ---------------- SIMT [M,256]@[256,256] (x@w1 and f@w2, exact fp32) ----------------
__global__ void __launch_bounds__(128) k_mm(const float* __restrict__ Ain,
                                            const float* __restrict__ B, int sel) {
    __shared__ float As[32][33];
    __shared__ float Bs[32][132];
    const float* A = sel ? g_fe : Ain;
    float*       C = sel ? g_g  : g_xw1;
    const int tid = threadIdx.x;
    const int la = tid & 31, wg = tid >> 5;
    const int tx = tid & 15, ty = tid >> 4;
    const int r0 = ty * 4, c0 = tx * 8;
    const int m0 = blockIdx.x * 32;
    const int dbase = blockIdx.y * 128;

    float acc[4][8];
#pragma unroll
    for (int i = 0; i < 4; i++)
#pragma unroll
        for (int j = 0; j < 8; j++) acc[i][j] = 0.0f;
    float ra[8]; float4 rb[8];
    auto load = [&](int kb) {
#pragma unroll
        for (int j = 0; j < 8; j++)
            ra[j] = A[(size_t)(m0 + wg + 4 * j) * DD + kb + la];
#pragma unroll
        for (int j = 0; j < 8; j++)
            rb[j] = *reinterpret_cast<const float4*>(
                &B[(size_t)(kb + wg + 4 * j) * DD + dbase + la * 4]);
    };
    auto store = [&]() {
#pragma unroll
        for (int j = 0; j < 8; j++) As[wg + 4 * j][la] = ra[j];
#pragma unroll
        for (int j = 0; j < 8; j++)
            *reinterpret_cast<float4*>(&Bs[wg + 4 * j][la * 4]) = rb[j];
    };
    load(0); store(); __syncthreads();
    for (int kt = 0; kt < DD / 32; kt++) {
        if (kt + 1 < DD / 32) load((kt + 1) * 32);
#pragma unroll 8
        for (int k = 0; k < 32; k++) {
            float a[4];
#pragma unroll
            for (int i = 0; i < 4; i++) a[i] = As[r0 + i][k];
            float4 b0 = *reinterpret_cast<const float4*>(&Bs[k][c0]);
            float4 b1 = *reinterpret_cast<const float4*>(&Bs[k][c0 + 4]);
            float b[8] = {b0.x, b0.y, b0.z, b0.w, b1.x, b1.y, b1.z, b1.w};
#pragma unroll
            for (int i = 0; i < 4; i++)
#pragma unroll
                for (int j = 0; j < 8; j++) acc[i][j] += a[i] * b[j];
        }
        __syncthreads();
        if (kt + 1 < DD / 32) { store(); __syncthreads(); }
    }
#pragma unroll
    for (int i = 0; i < 4; i++) {
        float* o = &C[(size_t)(m0 + r0 + i) * DD + dbase + c0];
        *reinterpret_cast<float4*>(o)     = make_float4(acc[i][0], acc[i][1], acc[i][2], acc[i][3]);
        *reinterpret_cast<float4*>(o + 4) = make_float4(acc[i][4], acc[i][5], acc[i][6], acc[i][7]);
    }
}

__global__ void k_node(const float* __restrict__ a1, const float* __restrict__ a22) {
    const int lane = threadIdx.x & 31;
    const int row = blockIdx.x * 8 + (threadIdx.x >> 5);
    const float* rp = &g_xw1[(size_t)row * DD];
    float f = 0.0f, r = 0.0f;
#pragma unroll
    for (int j = 0; j < 8; j++) {
        int d = lane + 32 * j;
        float v = lrelu(rp[d]);
        f += v * __ldg(&a1[d]);
        r += v * __ldg(&a22[d]);
    }
#pragma unroll
    for (int o = 16; o > 0; o >>= 1) {
        f += __shfl_down_sync(0xffffffffu, f, o);
        r += __shfl_down_sync(0xffffffffu, r, o);
    }
    if (lane == 0) { g_s1[row] = softexp8(f); g_r[row] = r; }
}

__global__ void k_cedge(const float* __restrict__ a21) {
    const int lane = threadIdx.x & 31;
    const int row = blockIdx.x * 8 + (threadIdx.x >> 5);
    const float* rp = &g_g[(size_t)row * DD];
    float c = 0.0f;
#pragma unroll
    for (int j = 0; j < 8; j++) {
        int d = lane + 32 * j;
        c += lrelu(rp[d]) * __ldg(&a21[d]);
    }
#pragma unroll
    for (int o = 16; o > 0; o >>= 1) c += __shfl_down_sync(0xffffffffu, c, o);
    if (lane == 0) g_c[row] = c;
}

// transpose + tf32 pre-round: 0: xw1->xw1T; 1: g->gT
// (rounded here so cp.async raw loads feed exact RNA-tf32 into the MMA)
__global__ void k_tr(int which) {
    __shared__ float t[32][33];
    const float* s = which ? g_g  : g_xw1;
    float*       d = which ? g_gT : g_xw1T;
    const int R = which ? NE : NN;
    const int c0 = blockIdx.x * 32, r0 = blockIdx.y * 32;
    const int x = threadIdx.x, y = threadIdx.y;
#pragma unroll
    for (int j = 0; j < 32; j += 8)
        t[y + j][x] = s[(size_t)(r0 + y + j) * DD + c0 + x];
    __syncthreads();
#pragma unroll
    for (int j = 0; j < 32; j += 8)
        d[(size_t)(c0 + y + j) * R + r0 + x] = __uint_as_float(tf32c(t[x][y + j]));
}

// ---------------- GEMM1: partial[s] = (H*s1)^T[128e slice] @ xw1 (k-split) ----------------
__global__ void __launch_bounds__(256, 1) k_gemm1(const float* __restrict__ H) {
    extern __shared__ uint32_t smu[];
    const uint32_t smb = su32(smu);
    const int tid = threadIdx.x;
    const int lane = tid & 31, wid = tid >> 5;
    const int wm = wid >> 2, wn = wid & 3;       // 2 x 4 warps, 64x64 tiles
    const int e0 = blockIdx.x * 128;
    const int s  = blockIdx.y;
    const int nsb = s * NCH;
    const int et = tid & 127, nq = tid >> 7;     // A fill: e col, n-half

    uint32_t* Ab[2] = { smu + OFF_A0, smu + OFF_A1 };
    uint32_t* Bb[2] = { smu + OFF_B0, smu + OFF_B1 };
    uint32_t  Bba[2] = { smb + OFF_B0 * 4, smb + OFF_B1 * 4 };
    float* red = (float*)(smu + OFF_RD);

    float acc[4][8][4];
#pragma unroll
    for (int mt = 0; mt < 4; mt++)
#pragma unroll
        for (int nt = 0; nt < 8; nt++)
#pragma unroll
            for (int q = 0; q < 4; q++) acc[mt][nt][q] = 0.0f;
    float cacc = 0.0f;
    float hst[16];

    auto ldgA = [&](int n0) {
#pragma unroll
        for (int i = 0; i < 16; i++) {
            const int n = n0 + nq * 16 + i;
            hst[i] = H[(size_t)n * NE + e0 + et] * __ldg(&g_s1[n]);
        }
    };
    auto stsA = [&](uint32_t* As) {
        uint32_t w[16];
#pragma unroll
        for (int i = 0; i < 16; i++) {
            w[i] = tf32c(hst[i]);
            cacc += __uint_as_float(w[i]);
        }
#pragma unroll
        for (int j = 0; j < 4; j++)
            *(uint4*)&As[et * PAD + nq * 16 + j * 4] =
                make_uint4(w[4 * j], w[4 * j + 1], w[4 * j + 2], w[4 * j + 3]);
    };
    auto cpaB = [&](int n0, uint32_t Ba) {
        const float* src = &g_xw1T[(size_t)tid * NN + n0];
        const uint32_t dst = Ba + tid * (PAD * 4);
#pragma unroll
        for (int c = 0; c < 8; c++) cpa16(dst + c * 16, src + c * 4);
    };

    cpaB(nsb, Bba[0]); CP_COMMIT();
    ldgA(nsb); stsA(Ab[0]);
    CP_WAIT0(); __syncthreads();

    const int T = NCH / 32;
    for (int t = 0; t < T; t++) {
        const int b = t & 1;
        if (t + 1 < T) {
            cpaB(nsb + (t + 1) * 32, Bba[b ^ 1]); CP_COMMIT();
            ldgA(nsb + (t + 1) * 32);
        }
        mma_stage64(Ab[b], Bb[b], acc, lane, wm, wn);
        if (t + 1 < T) { stsA(Ab[b ^ 1]); CP_WAIT0(); }
        __syncthreads();
    }

    red[nq * 128 + et] = cacc;
    __syncthreads();
    if (tid < 128)
        g_pcs[s * NE + e0 + tid] = red[tid] + red[128 + tid];

    const int qr = lane >> 2, qc2 = (lane & 3) * 2;
    float* base = g_p1 + (size_t)s * NE * DD;
#pragma unroll
    for (int mt = 0; mt < 4; mt++) {
        const int r = e0 + wm * 64 + mt * 16 + qr;
#pragma unroll
        for (int nt = 0; nt < 8; nt++) {
            const int c = wn * 64 + nt * 8 + qc2;
            *(float2*)&base[(size_t)r * DD + c] =
                make_float2(acc[mt][nt][0], acc[mt][nt][1]);
            *(float2*)&base[(size_t)(r + 8) * DD + c] =
                make_float2(acc[mt][nt][2], acc[mt][nt][3]);
        }
    }
}

// gemm1 reduction: g_fe = lrelu( (sum_s p1) / (sum_s pcs) )
__global__ void k_red1() {
    const int idx = blockIdx.x * 256 + threadIdx.x;    // float4 index over [NE][64]
    const int e = idx >> 6;
    float cs = g_pcs[e] + g_pcs[NE + e] + g_pcs[2 * NE + e] + g_pcs[3 * NE + e];
    float inv = 1.0f / cs;
    const float4* p = (const float4*)g_p1;
    const int SP = NE * (DD / 4);
    float4 v0 = p[idx], v1 = p[idx + SP], v2 = p[idx + 2 * SP], v3 = p[idx + 3 * SP];
    float4 o;
    o.x = lrelu((v0.x + v1.x + v2.x + v3.x) * inv);
    o.y = lrelu((v0.y + v1.y + v2.y + v3.y) * inv);
    o.z = lrelu((v0.z + v1.z + v2.z + v3.z) * inv);
    o.w = lrelu((v0.w + v1.w + v2.w + v3.w) * inv);
    ((float4*)g_fe)[idx] = o;
}

// ---------------- GEMM2: out = lrelu((W @ g) / rowsum), W = H*softexp8(c_e+r_n) ----------------
__global__ void __launch_bounds__(256, 1) k_gemm2(const float* __restrict__ H,
                                                  float* __restrict__ out) {
    extern __shared__ uint32_t smu[];
    const uint32_t smb = su32(smu);
    const int tid = threadIdx.x;
    const int lane = tid & 31, wid = tid >> 5;
    const int wm = wid >> 2, wn = wid & 3;
    const int n00 = blockIdx.x * 128;
    const int el = tid & 31, ng = tid >> 5;      // A fill: e lane, 16-row group

    uint32_t* Ab[2] = { smu + OFF_A0, smu + OFF_A1 };
    uint32_t* Bb[2] = { smu + OFF_B0, smu + OFF_B1 };
    uint32_t  Bba[2] = { smb + OFF_B0 * 4, smb + OFF_B1 * 4 };
    float* rsh  = (float*)(smu + OFF_RD);        // [128] r values
    float* rsum = rsh + 128;                     // [128] row sums

    if (tid < 128) rsh[tid] = g_r[n00 + tid];
    __syncthreads();

    float acc[4][8][4];
#pragma unroll
    for (int mt = 0; mt < 4; mt++)
#pragma unroll
        for (int nt = 0; nt < 8; nt++)
#pragma unroll
            for (int q = 0; q < 4; q++) acc[mt][nt][q] = 0.0f;
    float racc[16];
#pragma unroll
    for (int i = 0; i < 16; i++) racc[i] = 0.0f;
    float hst[16]; float cl = 0.0f;

    auto ldgA = [&](int e0s) {
        cl = __ldg(&g_c[e0s + el]);
#pragma unroll
        for (int i = 0; i < 16; i++)
            hst[i] = H[(size_t)(n00 + ng * 16 + i) * NE + e0s + el];
    };
    auto stsA = [&](uint32_t* As) {
#pragma unroll
        for (int i = 0; i < 16; i++) {
            float w = 0.0f;
            if (hst[i] != 0.0f)
                w = __uint_as_float(tf32c(softexp8(cl + rsh[ng * 16 + i])));
            racc[i] += w;
            As[(ng * 16 + i) * PAD + el] = __float_as_uint(w);
        }
    };
    auto cpaB = [&](int e0s, uint32_t Ba) {
        const float* src = &g_gT[(size_t)tid * NE + e0s];
        const uint32_t dst = Ba + tid * (PAD * 4);
#pragma unroll
        for (int c = 0; c < 8; c++) cpa16(dst + c * 16, src + c * 4);
    };

    cpaB(0, Bba[0]); CP_COMMIT();
    ldgA(0); stsA(Ab[0]);
    CP_WAIT0(); __syncthreads();

    const int T = NE / 32;
    for (int t = 0; t < T; t++) {
        const int b = t & 1;
        if (t + 1 < T) {
            cpaB((t + 1) * 32, Bba[b ^ 1]); CP_COMMIT();
            ldgA((t + 1) * 32);
        }
        mma_stage64(Ab[b], Bb[b], acc, lane, wm, wn);
        if (t + 1 < T) { stsA(Ab[b ^ 1]); CP_WAIT0(); }
        __syncthreads();
    }

    // rowsum: reduce racc over the 32 e-lanes of each warp
#pragma unroll
    for (int i = 0; i < 16; i++) {
        float v = racc[i];
#pragma unroll
        for (int o = 16; o > 0; o >>= 1) v += __shfl_xor_sync(0xffffffffu, v, o);
        if (lane == 0) rsum[ng * 16 + i] = v;
    }
    __syncthreads();

    const int qr = lane >> 2, qc2 = (lane & 3) * 2;
#pragma unroll
    for (int mt = 0; mt < 4; mt++) {
        const int rl = wm * 64 + mt * 16 + qr;
        const float inv0 = 1.0f / rsum[rl];
        const float inv1 = 1.0f / rsum[rl + 8];
#pragma unroll
        for (int nt = 0; nt < 8; nt++) {
            const int c = wn * 64 + nt * 8 + qc2;
            *(float2*)&out[(size_t)(n00 + rl) * DD + c] =
                make_float2(lrelu(acc[mt][nt][0] * inv0), lrelu(acc[mt][nt][1] * inv0));
            *(float2*)&out[(size_t)(n00 + rl + 8) * DD + c] =
                make_float2(lrelu(acc[mt][nt][2] * inv1), lrelu(acc[mt][nt][3] * inv1));
        }
    }
}

// =====================================================================
extern "C" void kernel_launch(void* const* d_in, const int* in_sizes, int n_in,
                              void* d_out, int out_size) {
    const float* x   = (const float*)d_in[0];
    const float* H   = (const float*)d_in[1];
    const float* w1  = (const float*)d_in[2];
    const float* w2  = (const float*)d_in[3];
    const float* a1  = (const float*)d_in[4];
    const float* a21 = (const float*)d_in[5];
    const float* a22 = (const float*)d_in[6];
    float* out = (float*)d_out;

    cudaFuncSetAttribute(k_gemm1, cudaFuncAttributeMaxDynamicSharedMemorySize, SMEMB);
    cudaFuncSetAttribute(k_gemm2, cudaFuncAttributeMaxDynamicSharedMemorySize, SMEMB);

    k_mm<<<dim3(NN / 32, 2), 128>>>(x, w1, 0);
    k_node<<<NN / 8, 256>>>(a1, a22);
    k_tr<<<dim3(DD / 32, NN / 32), dim3(32, 8)>>>(0);
    k_gemm1<<<dim3(NE / 128, KS), 256, SMEMB>>>(H);
    k_red1<<<NE * (DD / 4) / 256, 256>>>();
    k_mm<<<dim3(NE / 32, 2), 128>>>(nullptr, w2, 1);
    k_cedge<<<NE / 8, 256>>>(a21);
    k_tr<<<dim3(DD / 32, NE / 32), dim3(32, 8)>>>(1);
    k_gemm2<<<NN / 128, 256, SMEMB>>>(H, out);
}

// round 12
// speedup vs baseline: 1.1264x; 1.1264x over previous
#include <cuda_runtime.h>
#include <cstdint>

#define NN 16384
#define NE 4096
#define DD 256
#define KS 4             // k-splits for gemm1
#define NCH (NN / KS)    // 4096 nodes per split

// ---------------- scratch (device globals; no allocation allowed) ----------------
__device__ float g_xw1 [NN * DD];
__device__ float g_xw1T[DD * NN];   // tf32-rounded transpose of xw1
__device__ float g_fe  [NE * DD];
__device__ float g_g   [NE * DD];
__device__ float g_gT  [DD * NE];   // tf32-rounded transpose of g
__device__ float g_s1  [NN];
__device__ float g_r   [NN];
__device__ float g_c   [NE];
__device__ float g_p1  [KS * NE * DD];   // gemm1 k-split partials (16.8 MB)
__device__ float g_pcs [KS * NE];        // gemm1 colsum partials

__device__ __forceinline__ float lrelu(float v) { return v > 0.0f ? v : 0.1f * v; }

// exp(8*tanh(z/8)) via tanh(y) = 1 - 2/(e^{2y}+1) (exact, safe at +-inf)
__device__ __forceinline__ float softexp8(float z) {
    float v = __expf(z * 0.25f);
    float t = 1.0f - __fdividef(2.0f, v + 1.0f);
    return __expf(8.0f * t);
}

__device__ __forceinline__ uint32_t tf32c(float x) {
    uint32_t r; asm("cvt.rna.tf32.f32 %0, %1;" : "=r"(r) : "f"(x)); return r;
}

__device__ __forceinline__ uint32_t su32(const void* p) {
    uint32_t a;
    asm("{ .reg .u64 t; cvta.to.shared.u64 t, %1; cvt.u32.u64 %0, t; }" : "=r"(a) : "l"(p));
    return a;
}

__device__ __forceinline__ void mma8(float* d, const uint32_t a[4],
                                     uint32_t b0, uint32_t b1) {
    asm volatile(
        "mma.sync.aligned.m16n8k8.row.col.f32.tf32.tf32.f32 "
        "{%0,%1,%2,%3}, {%4,%5,%6,%7}, {%8,%9}, {%0,%1,%2,%3};"
        : "+f"(d[0]), "+f"(d[1]), "+f"(d[2]), "+f"(d[3])
        : "r"(a[0]), "r"(a[1]), "r"(a[2]), "r"(a[3]), "r"(b0), "r"(b1));
}

__device__ __forceinline__ void cpa16(uint32_t dst, const void* src) {
    asm volatile("cp.async.ca.shared.global [%0], [%1], 16;" :: "r"(dst), "l"(src));
}
#define CP_COMMIT() asm volatile("cp.async.commit_group;" ::: "memory")
#define CP_WAIT0()  asm volatile("cp.async.wait_group 0;" ::: "memory")

#define PAD 36
#define A_ST (128 * PAD)       // 4608 u32 per A buffer (128 rows x 32 k)
#define B_ST (128 * PAD)       // 4608 u32 per B buffer (128 rows x 32 k)
#define OFF_A0 0
#define OFF_A1 A_ST
#define OFF_B0 (2 * A_ST)
#define OFF_B1 (2 * A_ST + B_ST)
#define OFF_RD (2 * A_ST + 2 * B_ST)
#define SM_U32 (OFF_RD + 512)
#define SMEMB (SM_U32 * 4)     // 75776 bytes -> 2 CTAs / SM

// one 32-K stage: CTA tile 128x128, 8 warps (4x2), warp tile 32x64
__device__ __forceinline__ void mma_stage(const uint32_t* __restrict__ As,
                                          const uint32_t* __restrict__ Bs,
                                          float acc[2][8][4],
                                          int lane, int wm, int wn) {
    const int qr = lane >> 2, qc = lane & 3;
#pragma unroll
    for (int ks = 0; ks < 4; ks++) {
        const int kk = ks * 8;
        uint32_t af[2][4];
#pragma unroll
        for (int mt = 0; mt < 2; mt++) {
            const uint32_t* ap = As + (wm * 32 + mt * 16 + qr) * PAD + kk + qc;
            af[mt][0] = ap[0];
            af[mt][1] = ap[8 * PAD];
            af[mt][2] = ap[4];
            af[mt][3] = ap[8 * PAD + 4];
        }
#pragma unroll
        for (int nt = 0; nt < 8; nt++) {
            const uint32_t* bp = Bs + (wn * 64 + nt * 8 + qr) * PAD + kk + qc;
            uint32_t b0 = bp[0], b1 = bp[4];
#pragma unroll
            for (int mt = 0; mt < 2; mt++)
                mma8(acc[mt][nt], af[mt], b0, b1);
        }
    }
}

// ---------------- SIMT [M,256]@[256,256] (x@w1 and f@w2, exact fp32) ----------------
__global__ void __launch_bounds__(128) k_mm(const float* __restrict__ Ain,
                                            const float* __restrict__ B, int sel) {
    __shared__ float As[32][33];
    __shared__ float Bs[32][132];
    const float* A = sel ? g_fe : Ain;
    float*       C = sel ? g_g  : g_xw1;
    const int tid = threadIdx.x;
    const int la = tid & 31, wg = tid >> 5;
    const int tx = tid & 15, ty = tid >> 4;
    const int r0 = ty * 4, c0 = tx * 8;
    const int m0 = blockIdx.x * 32;
    const int dbase = blockIdx.y * 128;

    float acc[4][8];
#pragma unroll
    for (int i = 0; i < 4; i++)
#pragma unroll
        for (int j = 0; j < 8; j++) acc[i][j] = 0.0f;
    float ra[8]; float4 rb[8];
    auto load = [&](int kb) {
#pragma unroll
        for (int j = 0; j < 8; j++)
            ra[j] = A[(size_t)(m0 + wg + 4 * j) * DD + kb + la];
#pragma unroll
        for (int j = 0; j < 8; j++)
            rb[j] = *reinterpret_cast<const float4*>(
                &B[(size_t)(kb + wg + 4 * j) * DD + dbase + la * 4]);
    };
    auto store = [&]() {
#pragma unroll
        for (int j = 0; j < 8; j++) As[wg + 4 * j][la] = ra[j];
#pragma unroll
        for (int j = 0; j < 8; j++)
            *reinterpret_cast<float4*>(&Bs[wg + 4 * j][la * 4]) = rb[j];
    };
    load(0); store(); __syncthreads();
    for (int kt = 0; kt < DD / 32; kt++) {
        if (kt + 1 < DD / 32) load((kt + 1) * 32);
#pragma unroll 8
        for (int k = 0; k < 32; k++) {
            float a[4];
#pragma unroll
            for (int i = 0; i < 4; i++) a[i] = As[r0 + i][k];
            float4 b0 = *reinterpret_cast<const float4*>(&Bs[k][c0]);
            float4 b1 = *reinterpret_cast<const float4*>(&Bs[k][c0 + 4]);
            float b[8] = {b0.x, b0.y, b0.z, b0.w, b1.x, b1.y, b1.z, b1.w};
#pragma unroll
            for (int i = 0; i < 4; i++)
#pragma unroll
                for (int j = 0; j < 8; j++) acc[i][j] += a[i] * b[j];
        }
        __syncthreads();
        if (kt + 1 < DD / 32) { store(); __syncthreads(); }
    }
#pragma unroll
    for (int i = 0; i < 4; i++) {
        float* o = &C[(size_t)(m0 + r0 + i) * DD + dbase + c0];
        *reinterpret_cast<float4*>(o)     = make_float4(acc[i][0], acc[i][1], acc[i][2], acc[i][3]);
        *reinterpret_cast<float4*>(o + 4) = make_float4(acc[i][4], acc[i][5], acc[i][6], acc[i][7]);
    }
}

__global__ void k_node(const float* __restrict__ a1, const float* __restrict__ a22) {
    const int lane = threadIdx.x & 31;
    const int row = blockIdx.x * 8 + (threadIdx.x >> 5);
    const float* rp = &g_xw1[(size_t)row * DD];
    float f = 0.0f, r = 0.0f;
#pragma unroll
    for (int j = 0; j < 8; j++) {
        int d = lane + 32 * j;
        float v = lrelu(rp[d]);
        f += v * __ldg(&a1[d]);
        r += v * __ldg(&a22[d]);
    }
#pragma unroll
    for (int o = 16; o > 0; o >>= 1) {
        f += __shfl_down_sync(0xffffffffu, f, o);
        r += __shfl_down_sync(0xffffffffu, r, o);
    }
    if (lane == 0) { g_s1[row] = softexp8(f); g_r[row] = r; }
}

__global__ void k_cedge(const float* __restrict__ a21) {
    const int lane = threadIdx.x & 31;
    const int row = blockIdx.x * 8 + (threadIdx.x >> 5);
    const float* rp = &g_g[(size_t)row * DD];
    float c = 0.0f;
#pragma unroll
    for (int j = 0; j < 8; j++) {
        int d = lane + 32 * j;
        c += lrelu(rp[d]) * __ldg(&a21[d]);
    }
#pragma unroll
    for (int o = 16; o > 0; o >>= 1) c += __shfl_down_sync(0xffffffffu, c, o);
    if (lane == 0) g_c[row] = c;
}

// transpose + tf32 pre-round: 0: xw1->xw1T; 1: g->gT
__global__ void k_tr(int which) {
    __shared__ float t[32][33];
    const float* s = which ? g_g  : g_xw1;
    float*       d = which ? g_gT : g_xw1T;
    const int R = which ? NE : NN;
    const int c0 = blockIdx.x * 32, r0 = blockIdx.y * 32;
    const int x = threadIdx.x, y = threadIdx.y;
#pragma unroll
    for (int j = 0; j < 32; j += 8)
        t[y + j][x] = s[(size_t)(r0 + y + j) * DD + c0 + x];
    __syncthreads();
#pragma unroll
    for (int j = 0; j < 32; j += 8)
        d[(size_t)(c0 + y + j) * R + r0 + x] = __uint_as_float(tf32c(t[x][y + j]));
}

// ---------------- GEMM1: partial[s] = (H*s1)^T[128e] @ xw1[:,128d] (k-split) ----------------
__global__ void __launch_bounds__(256, 2) k_gemm1(const float* __restrict__ H) {
    extern __shared__ uint32_t smu[];
    const uint32_t smb = su32(smu);
    const int tid = threadIdx.x;
    const int lane = tid & 31, wid = tid >> 5;
    const int wm = wid >> 1, wn = wid & 1;       // 4 x 2 warps, 32x64 tiles
    const int e0 = blockIdx.x * 128;
    const int dbase = blockIdx.y * 128;
    const int s  = blockIdx.z;
    const int nsb = s * NCH;
    const int et = tid & 127, nq = tid >> 7;     // A fill: e col, n-half
    const int dt = tid >> 1,  bh = tid & 1;      // B fill: d row, half

    uint32_t* Ab[2] = { smu + OFF_A0, smu + OFF_A1 };
    uint32_t* Bb[2] = { smu + OFF_B0, smu + OFF_B1 };
    uint32_t  Bba[2] = { smb + OFF_B0 * 4, smb + OFF_B1 * 4 };
    float* red = (float*)(smu + OFF_RD);

    float acc[2][8][4];
#pragma unroll
    for (int mt = 0; mt < 2; mt++)
#pragma unroll
        for (int nt = 0; nt < 8; nt++)
#pragma unroll
            for (int q = 0; q < 4; q++) acc[mt][nt][q] = 0.0f;
    float cacc = 0.0f;
    float hst[16];

    auto ldgA = [&](int n0) {
#pragma unroll
        for (int i = 0; i < 16; i++) {
            const int n = n0 + nq * 16 + i;
            hst[i] = H[(size_t)n * NE + e0 + et] * __ldg(&g_s1[n]);
        }
    };
    auto stsA = [&](uint32_t* As) {
        uint32_t w[16];
#pragma unroll
        for (int i = 0; i < 16; i++) {
            w[i] = tf32c(hst[i]);
            cacc += __uint_as_float(w[i]);
        }
#pragma unroll
        for (int j = 0; j < 4; j++)
            *(uint4*)&As[et * PAD + nq * 16 + j * 4] =
                make_uint4(w[4 * j], w[4 * j + 1], w[4 * j + 2], w[4 * j + 3]);
    };
    auto cpaB = [&](int n0, uint32_t Ba) {
        const float* src = &g_xw1T[(size_t)(dbase + dt) * NN + n0 + bh * 16];
        const uint32_t dst = Ba + dt * (PAD * 4) + bh * 64;
#pragma unroll
        for (int c = 0; c < 4; c++) cpa16(dst + c * 16, src + c * 4);
    };

    cpaB(nsb, Bba[0]); CP_COMMIT();
    ldgA(nsb); stsA(Ab[0]);
    CP_WAIT0(); __syncthreads();

    const int T = NCH / 32;
    for (int t = 0; t < T; t++) {
        const int b = t & 1;
        if (t + 1 < T) {
            cpaB(nsb + (t + 1) * 32, Bba[b ^ 1]); CP_COMMIT();
            ldgA(nsb + (t + 1) * 32);
        }
        mma_stage(Ab[b], Bb[b], acc, lane, wm, wn);
        if (t + 1 < T) { stsA(Ab[b ^ 1]); CP_WAIT0(); }
        __syncthreads();
    }

    if (blockIdx.y == 0) {   // colsum identical across d-tiles; write once
        red[nq * 128 + et] = cacc;
        __syncthreads();
        if (tid < 128)
            g_pcs[s * NE + e0 + tid] = red[tid] + red[128 + tid];
    }

    const int qr = lane >> 2, qc2 = (lane & 3) * 2;
    float* base = g_p1 + (size_t)s * NE * DD;
#pragma unroll
    for (int mt = 0; mt < 2; mt++) {
        const int r = e0 + wm * 32 + mt * 16 + qr;
#pragma unroll
        for (int nt = 0; nt < 8; nt++) {
            const int c = dbase + wn * 64 + nt * 8 + qc2;
            *(float2*)&base[(size_t)r * DD + c] =
                make_float2(acc[mt][nt][0], acc[mt][nt][1]);
            *(float2*)&base[(size_t)(r + 8) * DD + c] =
                make_float2(acc[mt][nt][2], acc[mt][nt][3]);
        }
    }
}

// gemm1 reduction: g_fe = lrelu( (sum_s p1) / (sum_s pcs) )
__global__ void k_red1() {
    const int idx = blockIdx.x * 256 + threadIdx.x;    // float4 index over [NE][64]
    const int e = idx >> 6;
    float cs = g_pcs[e] + g_pcs[NE + e] + g_pcs[2 * NE + e] + g_pcs[3 * NE + e];
    float inv = 1.0f / cs;
    const float4* p = (const float4*)g_p1;
    const int SP = NE * (DD / 4);
    float4 v0 = p[idx], v1 = p[idx + SP], v2 = p[idx + 2 * SP], v3 = p[idx + 3 * SP];
    float4 o;
    o.x = lrelu((v0.x + v1.x + v2.x + v3.x) * inv);
    o.y = lrelu((v0.y + v1.y + v2.y + v3.y) * inv);
    o.z = lrelu((v0.z + v1.z + v2.z + v3.z) * inv);
    o.w = lrelu((v0.w + v1.w + v2.w + v3.w) * inv);
    ((float4*)g_fe)[idx] = o;
}

// ---------------- GEMM2: out = lrelu((W @ g) / rowsum), W = H*softexp8(c_e+r_n) ----------------
__global__ void __launch_bounds__(256, 2) k_gemm2(const float* __restrict__ H,
                                                  float* __restrict__ out) {
    extern __shared__ uint32_t smu[];
    const uint32_t smb = su32(smu);
    const int tid = threadIdx.x;
    const int lane = tid & 31, wid = tid >> 5;
    const int wm = wid >> 1, wn = wid & 1;
    const int n00 = blockIdx.x * 128;
    const int dbase = blockIdx.y * 128;
    const int el = tid & 31, ng = tid >> 5;      // A fill: e lane, 16-row group
    const int dt = tid >> 1,  bh = tid & 1;      // B fill

    uint32_t* Ab[2] = { smu + OFF_A0, smu + OFF_A1 };
    uint32_t* Bb[2] = { smu + OFF_B0, smu + OFF_B1 };
    uint32_t  Bba[2] = { smb + OFF_B0 * 4, smb + OFF_B1 * 4 };
    float* rsh  = (float*)(smu + OFF_RD);        // [128] r values
    float* rsum = rsh + 128;                     // [128] row sums

    if (tid < 128) rsh[tid] = g_r[n00 + tid];
    __syncthreads();

    float acc[2][8][4];
#pragma unroll
    for (int mt = 0; mt < 2; mt++)
#pragma unroll
        for (int nt = 0; nt < 8; nt++)
#pragma unroll
            for (int q = 0; q < 4; q++) acc[mt][nt][q] = 0.0f;
    float racc[16];
#pragma unroll
    for (int i = 0; i < 16; i++) racc[i] = 0.0f;
    float hst[16]; float cl = 0.0f;

    auto ldgA = [&](int e0s) {
        cl = __ldg(&g_c[e0s + el]);
#pragma unroll
        for (int i = 0; i < 16; i++)
            hst[i] = H[(size_t)(n00 + ng * 16 + i) * NE + e0s + el];
    };
    auto stsA = [&](uint32_t* As) {
#pragma unroll
        for (int i = 0; i < 16; i++) {
            float w = 0.0f;
            if (hst[i] != 0.0f)
                w = __uint_as_float(tf32c(softexp8(cl + rsh[ng * 16 + i])));
            racc[i] += w;
            As[(ng * 16 + i) * PAD + el] = __float_as_uint(w);
        }
    };
    auto cpaB = [&](int e0s, uint32_t Ba) {
        const float* src = &g_gT[(size_t)(dbase + dt) * NE + e0s + bh * 16];
        const uint32_t dst = Ba + dt * (PAD * 4) + bh * 64;
#pragma unroll
        for (int c = 0; c < 4; c++) cpa16(dst + c * 16, src + c * 4);
    };

    cpaB(0, Bba[0]); CP_COMMIT();
    ldgA(0); stsA(Ab[0]);
    CP_WAIT0(); __syncthreads();

    const int T = NE / 32;
    for (int t = 0; t < T; t++) {
        const int b = t & 1;
        if (t + 1 < T) {
            cpaB((t + 1) * 32, Bba[b ^ 1]); CP_COMMIT();
            ldgA((t + 1) * 32);
        }
        mma_stage(Ab[b], Bb[b], acc, lane, wm, wn);
        if (t + 1 < T) { stsA(Ab[b ^ 1]); CP_WAIT0(); }
        __syncthreads();
    }

    // rowsum: reduce racc over the 32 e-lanes of each warp
#pragma unroll
    for (int i = 0; i < 16; i++) {
        float v = racc[i];
#pragma unroll
        for (int o = 16; o > 0; o >>= 1) v += __shfl_xor_sync(0xffffffffu, v, o);
        if (lane == 0) rsum[ng * 16 + i] = v;
    }
    __syncthreads();

    const int qr = lane >> 2, qc2 = (lane & 3) * 2;
#pragma unroll
    for (int mt = 0; mt < 2; mt++) {
        const int rl = wm * 32 + mt * 16 + qr;
        const float inv0 = 1.0f / rsum[rl];
        const float inv1 = 1.0f / rsum[rl + 8];
#pragma unroll
        for (int nt = 0; nt < 8; nt++) {
            const int c = dbase + wn * 64 + nt * 8 + qc2;
            *(float2*)&out[(size_t)(n00 + rl) * DD + c] =
                make_float2(lrelu(acc[mt][nt][0] * inv0), lrelu(acc[mt][nt][1] * inv0));
            *(float2*)&out[(size_t)(n00 + rl + 8) * DD + c] =
                make_float2(lrelu(acc[mt][nt][2] * inv1), lrelu(acc[mt][nt][3] * inv1));
        }
    }
}

// =====================================================================
extern "C" void kernel_launch(void* const* d_in, const int* in_sizes, int n_in,
                              void* d_out, int out_size) {
    const float* x   = (const float*)d_in[0];
    const float* H   = (const float*)d_in[1];
    const float* w1  = (const float*)d_in[2];
    const float* w2  = (const float*)d_in[3];
    const float* a1  = (const float*)d_in[4];
    const float* a21 = (const float*)d_in[5];
    const float* a22 = (const float*)d_in[6];
    float* out = (float*)d_out;

    cudaFuncSetAttribute(k_gemm1, cudaFuncAttributeMaxDynamicSharedMemorySize, SMEMB);
    cudaFuncSetAttribute(k_gemm2, cudaFuncAttributeMaxDynamicSharedMemorySize, SMEMB);

    k_mm<<<dim3(NN / 32, 2), 128>>>(x, w1, 0);
    k_node<<<NN / 8, 256>>>(a1, a22);
    k_tr<<<dim3(DD / 32, NN / 32), dim3(32, 8)>>>(0);
    k_gemm1<<<dim3(NE / 128, 2, KS), 256, SMEMB>>>(H);
    k_red1<<<NE * (DD / 4) / 256, 256>>>();
    k_mm<<<dim3(NE / 32, 2), 128>>>(nullptr, w2, 1);
    k_cedge<<<NE / 8, 256>>>(a21);
    k_tr<<<dim3(DD / 32, NE / 32), dim3(32, 8)>>>(1);
    k_gemm2<<<dim3(NN / 128, 2), 256, SMEMB>>>(H, out);
}